// round 1
// baseline (speedup 1.0000x reference)
#include <cuda_runtime.h>
#include <cuda_bf16.h>
#include <math.h>

// Problem constants
#define PC_SRC   64000     // 1000*64 render points
#define REF_SRC  80000
#define N_PC     8000      // 64000/8
#define N_REF    10000     // 80000/8
#define TILE     1024      // ref/pc tile staged in smem (8 KB)

// Scratch (device globals; no allocation allowed)
__device__ float2   g_pc[N_PC];
__device__ float2   g_ref[N_REF];
__device__ unsigned g_min1[N_PC];    // min squared dist per pc point (uint bits)
__device__ unsigned g_min2[N_REF];   // min squared dist per ref point (uint bits)

// ---------------------------------------------------------------------------
// Prep: subsample gather (faithful to jnp.linspace fp32 semantics) + init mins
// ---------------------------------------------------------------------------
__global__ void prep_kernel(const float* __restrict__ pc_src,
                            const float* __restrict__ ref_src)
{
    int i = blockIdx.x * blockDim.x + threadIdx.x;
    if (i < N_PC) {
        // delta = (n-1)/(m-1) in fp32; idx = trunc(i * delta) in fp32
        float delta = (float)(PC_SRC - 1) / (float)(N_PC - 1);
        int idx = (int)((float)i * delta);
        if (idx > PC_SRC - 1) idx = PC_SRC - 1;
        g_pc[i] = make_float2(pc_src[2 * idx], pc_src[2 * idx + 1]);
        g_min1[i] = 0x7F800000u;  // +inf
    }
    if (i < N_REF) {
        float delta = (float)(REF_SRC - 1) / (float)(N_REF - 1);
        int idx = (int)((float)i * delta);
        if (idx > REF_SRC - 1) idx = REF_SRC - 1;
        g_ref[i] = make_float2(ref_src[2 * idx], ref_src[2 * idx + 1]);
        g_min2[i] = 0x7F800000u;
    }
}

// ---------------------------------------------------------------------------
// Min pass. DIR=true : P = pc (8000), R = ref (10000), writes g_min1
//           DIR=false: P = ref,       R = pc,          writes g_min2
// blockIdx.x tiles P (256 pts/block, 1/thread); blockIdx.y tiles R (1024/block).
// All threads in a warp read the SAME smem ref point each iter -> broadcast.
// ---------------------------------------------------------------------------
template <bool DIR>
__global__ void min_pass_kernel()
{
    const float2* __restrict__ P = DIR ? g_pc : g_ref;
    const float2* __restrict__ R = DIR ? g_ref : g_pc;
    unsigned* __restrict__ gmin  = DIR ? g_min1 : g_min2;
    const int np = DIR ? N_PC : N_REF;
    const int nr = DIR ? N_REF : N_PC;

    __shared__ float2 sR[TILE];
    int base = blockIdx.y * TILE;
    for (int j = threadIdx.x; j < TILE; j += blockDim.x) {
        int rj = base + j;
        // out-of-range pads -> huge distance, never selected by fminf
        sR[j] = (rj < nr) ? R[rj] : make_float2(1e30f, 1e30f);
    }
    __syncthreads();

    int i = blockIdx.x * blockDim.x + threadIdx.x;
    float2 p = (i < np) ? P[i] : make_float2(0.0f, 0.0f);

    float m = __int_as_float(0x7F800000);  // +inf
#pragma unroll 8
    for (int j = 0; j < TILE; j++) {
        float dx = p.x - sR[j].x;
        float dy = p.y - sR[j].y;
        float d2 = fmaf(dx, dx, dy * dy);
        m = fminf(m, d2);
    }

    if (i < np) atomicMin(&gmin[i], __float_as_uint(m));
}

// ---------------------------------------------------------------------------
// Final reduce: out = (mean(sqrt(min1)) + mean(sqrt(min2))) / 2
// ---------------------------------------------------------------------------
__global__ void reduce_kernel(float* __restrict__ out)
{
    __shared__ double warp_s1[32];
    __shared__ double warp_s2[32];
    int tid = threadIdx.x;

    double s1 = 0.0, s2 = 0.0;
    for (int i = tid; i < N_PC; i += blockDim.x)
        s1 += (double)sqrtf(__uint_as_float(g_min1[i]));
    for (int i = tid; i < N_REF; i += blockDim.x)
        s2 += (double)sqrtf(__uint_as_float(g_min2[i]));

    // warp reduce
    for (int off = 16; off > 0; off >>= 1) {
        s1 += __shfl_down_sync(0xFFFFFFFFu, s1, off);
        s2 += __shfl_down_sync(0xFFFFFFFFu, s2, off);
    }
    int wid = tid >> 5, lid = tid & 31;
    if (lid == 0) { warp_s1[wid] = s1; warp_s2[wid] = s2; }
    __syncthreads();

    if (wid == 0) {
        int nwarps = blockDim.x >> 5;
        s1 = (lid < nwarps) ? warp_s1[lid] : 0.0;
        s2 = (lid < nwarps) ? warp_s2[lid] : 0.0;
        for (int off = 16; off > 0; off >>= 1) {
            s1 += __shfl_down_sync(0xFFFFFFFFu, s1, off);
            s2 += __shfl_down_sync(0xFFFFFFFFu, s2, off);
        }
        if (lid == 0)
            out[0] = (float)((s1 / (double)N_PC + s2 / (double)N_REF) * 0.5);
    }
}

// ---------------------------------------------------------------------------
extern "C" void kernel_launch(void* const* d_in, const int* in_sizes, int n_in,
                              void* d_out, int out_size)
{
    const float* pc_src  = (const float*)d_in[0];  // (1000,64,2) fp32
    const float* ref_src = (const float*)d_in[1];  // (80000,2) fp32
    float* out = (float*)d_out;

    // prep: cover max(N_PC, N_REF)=10000 threads
    prep_kernel<<<(N_REF + 255) / 256, 256>>>(pc_src, ref_src);

    // pass A: pc rows (8000 -> 32 blocks of 256), ref tiles (10000 -> 10 tiles)
    {
        dim3 grid((N_PC + 255) / 256, (N_REF + TILE - 1) / TILE);
        min_pass_kernel<true><<<grid, 256>>>();
    }
    // pass B: ref rows (10000 -> 40 blocks), pc tiles (8000 -> 8 tiles)
    {
        dim3 grid((N_REF + 255) / 256, (N_PC + TILE - 1) / TILE);
        min_pass_kernel<false><<<grid, 256>>>();
    }

    reduce_kernel<<<1, 1024>>>(out);
}

// round 3
// speedup vs baseline: 1.8251x; 1.8251x over previous
#include <cuda_runtime.h>
#include <cuda_bf16.h>
#include <math.h>

// Problem constants
#define PC_SRC   64000     // 1000*64 render points
#define REF_SRC  80000
#define N_PC     8000      // 64000/8
#define N_REF    10000     // 80000/8
#define TILE     1024      // R-tile staged in smem (16 KB as float4)
#define YT_A     10        // ceil(10000/1024) tiles for pass A (R = ref)
#define YT_B     8         // ceil(8000/1024)  tiles for pass B (R = pc)
#define XB_A     16        // ceil(8000/512)  x-blocks, 512 pts/block
#define XB_B     20        // ceil(10000/512)

// Scratch (device globals; no allocation allowed)
__device__ float2 g_pc[N_PC];              // centered at (0.5,0.5)
__device__ float2 g_ref[N_REF];
__device__ float  g_partA[YT_A * N_PC];    // per-tile min of (|r|^2 - 2 p.r) for pc pts
__device__ float  g_partB[YT_B * N_REF];   // same for ref pts
__device__ double g_sum;
__device__ unsigned g_ticket;

#define FINF __int_as_float(0x7F800000)

// ---------------------------------------------------------------------------
// Prep: subsample gather (faithful jnp.linspace fp32 semantics), center at 0.5,
// reset accumulators.
// ---------------------------------------------------------------------------
__global__ void prep_kernel(const float* __restrict__ pc_src,
                            const float* __restrict__ ref_src)
{
    int i = blockIdx.x * blockDim.x + threadIdx.x;
    if (i == 0) { g_sum = 0.0; g_ticket = 0u; }
    if (i < N_PC) {
        float delta = (float)(PC_SRC - 1) / (float)(N_PC - 1);  // fp32 step
        int idx = (int)((float)i * delta);                      // fp32 mul, trunc
        if (idx > PC_SRC - 1) idx = PC_SRC - 1;
        g_pc[i] = make_float2(pc_src[2 * idx] - 0.5f, pc_src[2 * idx + 1] - 0.5f);
    }
    if (i < N_REF) {
        float delta = (float)(REF_SRC - 1) / (float)(N_REF - 1);
        int idx = (int)((float)i * delta);
        if (idx > REF_SRC - 1) idx = REF_SRC - 1;
        g_ref[i] = make_float2(ref_src[2 * idx] - 0.5f, ref_src[2 * idx + 1] - 0.5f);
    }
}

// ---------------------------------------------------------------------------
// Fused min pass, both directions via blockIdx.z.
// z=0: P = pc (8000),  R = ref (10000) -> g_partA
// z=1: P = ref (10000), R = pc (8000)  -> g_partB
// Each block: 256 threads * 2 points; one R-tile of 1024 in smem as float4
// (-2rx, -2ry, |r|^2, 0). Inner loop: 2 FFMA + 1 FMNMX per pair, smem broadcast.
// Writes per-tile partial min (no atomics).
// ---------------------------------------------------------------------------
__global__ void pass_kernel()
{
    const int z = blockIdx.z;
    if (z == 0) { if (blockIdx.x >= XB_A) return; }
    else        { if (blockIdx.y >= YT_B) return; }

    const float2* __restrict__ P = z ? g_ref : g_pc;
    const float2* __restrict__ R = z ? g_pc  : g_ref;
    float* __restrict__ part     = z ? g_partB : g_partA;
    const int np = z ? N_REF : N_PC;
    const int nr = z ? N_PC  : N_REF;

    __shared__ float4 sR[TILE];
    const int tid = threadIdx.x;
    const int base = blockIdx.y * TILE;
    for (int j = tid; j < TILE; j += 256) {
        int rj = base + j;
        if (rj < nr) {
            float2 r = R[rj];
            sR[j] = make_float4(-2.0f * r.x, -2.0f * r.y,
                                fmaf(r.x, r.x, r.y * r.y), 0.0f);
        } else {
            sR[j] = make_float4(0.0f, 0.0f, 1e30f, 0.0f);
        }
    }
    __syncthreads();

    const int i0 = blockIdx.x * 512 + tid;
    const int i1 = i0 + 256;
    float2 p0 = (i0 < np) ? P[i0] : make_float2(0.0f, 0.0f);
    float2 p1 = (i1 < np) ? P[i1] : make_float2(0.0f, 0.0f);

    float m0a = FINF, m0b = FINF, m1a = FINF, m1b = FINF;
#pragma unroll 4
    for (int j = 0; j < TILE; j += 2) {
        float4 ra = sR[j];
        float4 rb = sR[j + 1];
        float t0a = fmaf(p0.x, ra.x, fmaf(p0.y, ra.y, ra.z));
        float t1a = fmaf(p1.x, ra.x, fmaf(p1.y, ra.y, ra.z));
        float t0b = fmaf(p0.x, rb.x, fmaf(p0.y, rb.y, rb.z));
        float t1b = fmaf(p1.x, rb.x, fmaf(p1.y, rb.y, rb.z));
        m0a = fminf(m0a, t0a);
        m1a = fminf(m1a, t1a);
        m0b = fminf(m0b, t0b);
        m1b = fminf(m1b, t1b);
    }
    float m0 = fminf(m0a, m0b);
    float m1 = fminf(m1a, m1b);

    const int yoff = blockIdx.y * np;
    if (i0 < np) part[yoff + i0] = m0;
    if (i1 < np) part[yoff + i1] = m1;
}

// ---------------------------------------------------------------------------
// Finish: min over tiles, d = sqrt(max(0, |p|^2 + t_min)), weighted mean
// accumulated in double; last block (ticket) writes the scalar output.
// Blocks 0..31 -> pc points, 32..71 -> ref points.
// ---------------------------------------------------------------------------
__global__ void finish_kernel(float* __restrict__ out)
{
    __shared__ double warp_s[8];
    const int b = blockIdx.x;
    const int tid = threadIdx.x;
    double local = 0.0;

    if (b < 32) {
        int i = b * 256 + tid;
        if (i < N_PC) {
            float2 p = g_pc[i];
            float pp = fmaf(p.x, p.x, p.y * p.y);
            float m = FINF;
#pragma unroll
            for (int y = 0; y < YT_A; y++)
                m = fminf(m, g_partA[y * N_PC + i]);
            float d2 = fmaxf(pp + m, 0.0f);
            local = (double)sqrtf(d2) * (0.5 / (double)N_PC);
        }
    } else {
        int i = (b - 32) * 256 + tid;
        if (i < N_REF) {
            float2 p = g_ref[i];
            float pp = fmaf(p.x, p.x, p.y * p.y);
            float m = FINF;
#pragma unroll
            for (int y = 0; y < YT_B; y++)
                m = fminf(m, g_partB[y * N_REF + i]);
            float d2 = fmaxf(pp + m, 0.0f);
            local = (double)sqrtf(d2) * (0.5 / (double)N_REF);
        }
    }

    // block reduce (256 threads = 8 warps)
    for (int off = 16; off > 0; off >>= 1)
        local += __shfl_down_sync(0xFFFFFFFFu, local, off);
    int wid = tid >> 5, lid = tid & 31;
    if (lid == 0) warp_s[wid] = local;
    __syncthreads();
    if (wid == 0) {
        local = (lid < 8) ? warp_s[lid] : 0.0;
        for (int off = 4; off > 0; off >>= 1)
            local += __shfl_down_sync(0xFFFFFFFFu, local, off);
        if (lid == 0) {
            atomicAdd(&g_sum, local);
            __threadfence();
            unsigned t = atomicInc(&g_ticket, 0xFFFFFFFFu);
            if (t == 71u) {
                // last block: read final sum and publish
                double s = atomicAdd(&g_sum, 0.0);
                out[0] = (float)s;
            }
        }
    }
}

// ---------------------------------------------------------------------------
extern "C" void kernel_launch(void* const* d_in, const int* in_sizes, int n_in,
                              void* d_out, int out_size)
{
    const float* pc_src  = (const float*)d_in[0];  // (1000,64,2) fp32
    const float* ref_src = (const float*)d_in[1];  // (80000,2) fp32
    float* out = (float*)d_out;

    prep_kernel<<<(N_REF + 255) / 256, 256>>>(pc_src, ref_src);

    dim3 grid(XB_B, YT_A, 2);   // (20, 10, 2); inactive corners early-exit
    pass_kernel<<<grid, 256>>>();

    finish_kernel<<<72, 256>>>(out);
}

// round 5
// speedup vs baseline: 2.0136x; 1.1033x over previous
#include <cuda_runtime.h>
#include <cuda_bf16.h>
#include <math.h>

// Problem constants
#define PC_SRC   64000
#define REF_SRC  80000
#define N_PC     8000
#define N_REF    10000
#define TILE     1024
#define HALF_TILE 512
#define YT_A     10          // ceil(10000/1024) ref tiles (for pc points)
#define YT_B     8           // ceil(8000/1024)  pc tiles (for ref points)
#define XB_A     32          // ceil(8000/256)
#define XB_B     40          // ceil(10000/256)
#define NBLK_A   (XB_A * YT_A)   // 320
#define NBLK_B   (XB_B * YT_B)   // 320
#define NBLK     (NBLK_A + NBLK_B)
#define THREADS  64
#define PTSB     256         // points per block (4 per thread)

#define FINF __int_as_float(0x7F800000)

// Scratch (device globals; allocation is forbidden)
__device__ float  g_partA[YT_A * N_PC];   // per-tile min of (pp + |r|^2 - 2 p.r)
__device__ float  g_partB[YT_B * N_REF];
__device__ double g_sum;
__device__ unsigned g_ticket;

typedef unsigned long long ull;

static __device__ __forceinline__ ull pack2(float lo, float hi) {
    ull r; asm("mov.b64 %0, {%1, %2};" : "=l"(r) : "f"(lo), "f"(hi)); return r;
}
static __device__ __forceinline__ void unpack2(ull v, float& lo, float& hi) {
    asm("mov.b64 {%0, %1}, %2;" : "=f"(lo), "=f"(hi) : "l"(v));
}
static __device__ __forceinline__ ull fma2(ull a, ull b, ull c) {
    ull d; asm("fma.rn.f32x2 %0, %1, %2, %3;" : "=l"(d) : "l"(a), "l"(b), "l"(c));
    return d;
}

// ---------------------------------------------------------------------------
// Fused pass: gathers subsampled points on the fly (faithful fp32 linspace
// semantics), stages packed ref tiles in smem, runs f32x2 inner loop, and
// writes per-(point, tile) partial mins of the full squared distance.
//   bid <  320: P = pc (8000 pts),  R = ref (10000) -> g_partA
//   bid >= 320: P = ref (10000),    R = pc  (8000)  -> g_partB
// ---------------------------------------------------------------------------
__global__ void __launch_bounds__(THREADS) pass_kernel(
    const float* __restrict__ pc_src, const float* __restrict__ ref_src)
{
    const int bid = blockIdx.x;
    const int tid = threadIdx.x;
    if (bid == 0 && tid == 0) { g_sum = 0.0; g_ticket = 0u; }  // reset for finish

    int z, xb, yb;
    if (bid < NBLK_A) { z = 0; xb = bid % XB_A; yb = bid / XB_A; }
    else { int b = bid - NBLK_A; z = 1; xb = b % XB_B; yb = b / XB_B; }

    const float* __restrict__ Psrc = z ? ref_src : pc_src;
    const float* __restrict__ Rsrc = z ? pc_src  : ref_src;
    const int np     = z ? N_REF   : N_PC;
    const int nr     = z ? N_PC    : N_REF;
    const int nsrcP  = z ? REF_SRC : PC_SRC;
    const int nsrcR  = z ? PC_SRC  : REF_SRC;
    const float deltaP = (float)(nsrcP - 1) / (float)(np - 1);
    const float deltaR = (float)(nsrcR - 1) / (float)(nr - 1);
    float* __restrict__ part = z ? g_partB : g_partA;

    // Packed tile: sXY[j] = (-2rx0, -2rx1, -2ry0, -2ry1), sZ[j] = (|r0|^2, |r1|^2)
    __shared__ float4 sXY[HALF_TILE];
    __shared__ float2 sZ[HALF_TILE];

    const int rbase = yb * TILE;
    for (int jp = tid; jp < HALF_TILE; jp += THREADS) {
        float x0 = 0.f, y0 = 0.f, z0 = 1e30f;
        float x1 = 0.f, y1 = 0.f, z1 = 1e30f;
        int r0i = rbase + 2 * jp;
        int r1i = r0i + 1;
        if (r0i < nr) {
            int idx = (int)((float)r0i * deltaR);          // fp32 mul + trunc
            if (idx > nsrcR - 1) idx = nsrcR - 1;
            float rx = Rsrc[2 * idx] - 0.5f, ry = Rsrc[2 * idx + 1] - 0.5f;
            x0 = -2.f * rx; y0 = -2.f * ry; z0 = fmaf(rx, rx, ry * ry);
        }
        if (r1i < nr) {
            int idx = (int)((float)r1i * deltaR);
            if (idx > nsrcR - 1) idx = nsrcR - 1;
            float rx = Rsrc[2 * idx] - 0.5f, ry = Rsrc[2 * idx + 1] - 0.5f;
            x1 = -2.f * rx; y1 = -2.f * ry; z1 = fmaf(rx, rx, ry * ry);
        }
        sXY[jp] = make_float4(x0, x1, y0, y1);
        sZ[jp]  = make_float2(z0, z1);
    }
    __syncthreads();

    // 4 points per thread, gathered on the fly
    ull px2[4], py2[4];
    float pp[4];
    const int ibase = xb * PTSB + tid;
#pragma unroll
    for (int k = 0; k < 4; k++) {
        int i = ibase + k * THREADS;
        int ic = (i < np) ? i : (np - 1);
        int idx = (int)((float)ic * deltaP);
        if (idx > nsrcP - 1) idx = nsrcP - 1;
        float px = Psrc[2 * idx] - 0.5f, py = Psrc[2 * idx + 1] - 0.5f;
        px2[k] = pack2(px, px);
        py2[k] = pack2(py, py);
        pp[k]  = fmaf(px, px, py * py);
    }

    float m[8];
#pragma unroll
    for (int k = 0; k < 8; k++) m[k] = FINF;

#pragma unroll 8
    for (int j = 0; j < HALF_TILE; j++) {
        float4 xy = sXY[j];
        float2 zz = sZ[j];
        ull rx2 = pack2(xy.x, xy.y);
        ull ry2 = pack2(xy.z, xy.w);
        ull rz2 = pack2(zz.x, zz.y);
#pragma unroll
        for (int k = 0; k < 4; k++) {
            ull t = fma2(px2[k], rx2, fma2(py2[k], ry2, rz2));
            float tlo, thi; unpack2(t, tlo, thi);
            m[2 * k]     = fminf(m[2 * k],     tlo);
            m[2 * k + 1] = fminf(m[2 * k + 1], thi);
        }
    }

    const int yoff = yb * np;
#pragma unroll
    for (int k = 0; k < 4; k++) {
        int i = ibase + k * THREADS;
        if (i < np)
            part[yoff + i] = pp[k] + fminf(m[2 * k], m[2 * k + 1]);
    }
}

// ---------------------------------------------------------------------------
// Finish: per point min over tiles, d = sqrt(max(m,0)); weighted double sum;
// last block (ticket) publishes the scalar. Blocks 0..31 pc, 32..71 ref.
// ---------------------------------------------------------------------------
__global__ void __launch_bounds__(256) finish_kernel(float* __restrict__ out)
{
    __shared__ double warp_s[8];
    const int b = blockIdx.x;
    const int tid = threadIdx.x;
    double local = 0.0;

    if (b < 32) {
        int i = b * 256 + tid;
        if (i < N_PC) {
            float m = FINF;
#pragma unroll
            for (int y = 0; y < YT_A; y++)
                m = fminf(m, g_partA[y * N_PC + i]);
            local = (double)sqrtf(fmaxf(m, 0.0f)) * (0.5 / (double)N_PC);
        }
    } else {
        int i = (b - 32) * 256 + tid;
        if (i < N_REF) {
            float m = FINF;
#pragma unroll
            for (int y = 0; y < YT_B; y++)
                m = fminf(m, g_partB[y * N_REF + i]);
            local = (double)sqrtf(fmaxf(m, 0.0f)) * (0.5 / (double)N_REF);
        }
    }

    for (int off = 16; off > 0; off >>= 1)
        local += __shfl_down_sync(0xFFFFFFFFu, local, off);
    int wid = tid >> 5, lid = tid & 31;
    if (lid == 0) warp_s[wid] = local;
    __syncthreads();
    if (wid == 0) {
        local = (lid < 8) ? warp_s[lid] : 0.0;
        for (int off = 4; off > 0; off >>= 1)
            local += __shfl_down_sync(0xFFFFFFFFu, local, off);
        if (lid == 0) {
            atomicAdd(&g_sum, local);
            __threadfence();
            unsigned t = atomicInc(&g_ticket, 0xFFFFFFFFu);
            if (t == 71u) {
                double s = atomicAdd(&g_sum, 0.0);
                out[0] = (float)s;
            }
        }
    }
}

// ---------------------------------------------------------------------------
extern "C" void kernel_launch(void* const* d_in, const int* in_sizes, int n_in,
                              void* d_out, int out_size)
{
    const float* pc_src  = (const float*)d_in[0];  // (1000,64,2) fp32
    const float* ref_src = (const float*)d_in[1];  // (80000,2)  fp32
    float* out = (float*)d_out;

    pass_kernel<<<NBLK, THREADS>>>(pc_src, ref_src);
    finish_kernel<<<72, 256>>>(out);
}

// round 7
// speedup vs baseline: 2.1646x; 1.0750x over previous
#include <cuda_runtime.h>
#include <cuda_bf16.h>
#include <math.h>

// Problem constants
#define PC_SRC   64000
#define REF_SRC  80000
#define N_PC     8000
#define N_REF    10000

#define GRID     296           // 2 blocks per SM on 148-SM GB300; all co-resident
#define THREADS  256
#define TILE     256           // refs per smem tile
#define HTILE    128           // packed (2-ref) tile entries
#define PTS      512           // points per chunk (2 per thread)

#define XC_A     16            // ceil(8000/512)
#define YT_A     40            // ceil(10000/256)
#define XC_B     20            // ceil(10000/512)
#define YT_B     32            // ceil(8000/256)
#define NCHUNK_A (XC_A * YT_A) // 640
#define NCHUNK_B (XC_B * YT_B) // 640
#define NCHUNK   (NCHUNK_A + NCHUNK_B)

#define FINF __int_as_float(0x7F800000)

// Device-global scratch (allocation forbidden)
__device__ float4  g_pcS[N_PC];            // (-2x, -2y, |c|^2, 0), centered
__device__ float4  g_refS[N_REF];
__device__ float   g_partA[YT_A * N_PC];   // per-tile min of full squared dist
__device__ float   g_partB[YT_B * N_REF];
__device__ double  g_sum;
__device__ unsigned g_bar1, g_bar2, g_done, g_ticket;

typedef unsigned long long ull;

static __device__ __forceinline__ ull pack2(float lo, float hi) {
    ull r; asm("mov.b64 %0, {%1, %2};" : "=l"(r) : "f"(lo), "f"(hi)); return r;
}
static __device__ __forceinline__ void unpack2(ull v, float& lo, float& hi) {
    asm("mov.b64 {%0, %1}, %2;" : "=f"(lo), "=f"(hi) : "l"(v));
}
static __device__ __forceinline__ ull fma2(ull a, ull b, ull c) {
    ull d; asm("fma.rn.f32x2 %0, %1, %2, %3;" : "=l"(d) : "l"(a), "l"(b), "l"(c));
    return d;
}

__global__ void __launch_bounds__(THREADS) chamfer_kernel(
    const float* __restrict__ pc_src, const float* __restrict__ ref_src,
    float* __restrict__ out)
{
    const int tid = threadIdx.x;
    const int bid = blockIdx.x;
    const int gtid = bid * THREADS + tid;
    const bool leader = (tid == 0);

    __shared__ float4 sXY[HTILE];   // (-2rx0,-2rx1,-2ry0,-2ry1)
    __shared__ float2 sZ[HTILE];    // (|r0|^2, |r1|^2)
    __shared__ unsigned s_w;
    __shared__ double warp_s[8];

    // ---------------- Phase 0: stage subsampled, centered, preprocessed points
    if (gtid < N_PC) {
        float delta = (float)(PC_SRC - 1) / (float)(N_PC - 1);  // fp32 linspace
        int idx = (int)((float)gtid * delta);                   // fp32 mul+trunc
        if (idx > PC_SRC - 1) idx = PC_SRC - 1;
        float x = pc_src[2 * idx] - 0.5f, y = pc_src[2 * idx + 1] - 0.5f;
        g_pcS[gtid] = make_float4(-2.0f * x, -2.0f * y, fmaf(x, x, y * y), 0.0f);
    }
    if (gtid < N_REF) {
        float delta = (float)(REF_SRC - 1) / (float)(N_REF - 1);
        int idx = (int)((float)gtid * delta);
        if (idx > REF_SRC - 1) idx = REF_SRC - 1;
        float x = ref_src[2 * idx] - 0.5f, y = ref_src[2 * idx + 1] - 0.5f;
        g_refS[gtid] = make_float4(-2.0f * x, -2.0f * y, fmaf(x, x, y * y), 0.0f);
    }
    __threadfence();
    __syncthreads();
    if (leader) {
        atomicAdd(&g_bar1, 1u);
        while (*((volatile unsigned*)&g_bar1) < GRID) __nanosleep(32);
    }
    __syncthreads();

    // ---------------- Phase 1: dynamic chunk loop (1280 chunks of 512pts x 256refs)
    for (;;) {
        if (leader) s_w = atomicAdd(&g_ticket, 1u);
        __syncthreads();                       // also guards smem tile overwrite
        const unsigned w = s_w;
        if (w >= NCHUNK) break;

        int z, xc, yc;
        if (w < NCHUNK_A) { z = 0; xc = w % XC_A; yc = w / XC_A; }
        else { unsigned v = w - NCHUNK_A; z = 1; xc = v % XC_B; yc = v / XC_B; }

        const float4* __restrict__ P = z ? g_refS : g_pcS;
        const float4* __restrict__ R = z ? g_pcS  : g_refS;
        float* __restrict__ part     = z ? g_partB : g_partA;
        const int np = z ? N_REF : N_PC;
        const int nr = z ? N_PC  : N_REF;

        // stage packed tile (coalesced float4 reads of preprocessed data)
        const int rbase = yc * TILE;
        for (int jp = tid; jp < HTILE; jp += THREADS) {
            int r0 = rbase + 2 * jp, r1 = r0 + 1;
            float4 a = (r0 < nr) ? R[r0] : make_float4(0.f, 0.f, 1e30f, 0.f);
            float4 b = (r1 < nr) ? R[r1] : make_float4(0.f, 0.f, 1e30f, 0.f);
            sXY[jp] = make_float4(a.x, b.x, a.y, b.y);
            sZ[jp]  = make_float2(a.z, b.z);
        }
        __syncthreads();

        // 2 points per thread
        const int i0 = xc * PTS + tid;
        const int i1 = i0 + THREADS;
        float4 p0 = P[(i0 < np) ? i0 : (np - 1)];
        float4 p1 = P[(i1 < np) ? i1 : (np - 1)];
        const ull px0 = pack2(-0.5f * p0.x, -0.5f * p0.x);
        const ull py0 = pack2(-0.5f * p0.y, -0.5f * p0.y);
        const ull px1 = pack2(-0.5f * p1.x, -0.5f * p1.x);
        const ull py1 = pack2(-0.5f * p1.y, -0.5f * p1.y);

        float m0a = FINF, m0b = FINF, m1a = FINF, m1b = FINF;
#pragma unroll 8
        for (int j = 0; j < HTILE; j++) {
            float4 xy = sXY[j];
            float2 zz = sZ[j];
            ull rx2 = pack2(xy.x, xy.y);
            ull ry2 = pack2(xy.z, xy.w);
            ull rz2 = pack2(zz.x, zz.y);
            ull t0 = fma2(px0, rx2, fma2(py0, ry2, rz2));
            ull t1 = fma2(px1, rx2, fma2(py1, ry2, rz2));
            float t0l, t0h, t1l, t1h;
            unpack2(t0, t0l, t0h);
            unpack2(t1, t1l, t1h);
            m0a = fminf(m0a, t0l); m0b = fminf(m0b, t0h);
            m1a = fminf(m1a, t1l); m1b = fminf(m1b, t1h);
        }

        const int yoff = yc * np;
        if (i0 < np) part[yoff + i0] = p0.z + fminf(m0a, m0b);
        if (i1 < np) part[yoff + i1] = p1.z + fminf(m1a, m1b);
    }

    // ---------------- barrier 2 (partials visible to all)
    __threadfence();
    __syncthreads();
    if (leader) {
        atomicAdd(&g_bar2, 1u);
        while (*((volatile unsigned*)&g_bar2) < GRID) __nanosleep(32);
    }
    __syncthreads();

    // ---------------- Phase 2: finish reduction (18000 points over 75776 threads)
    double local = 0.0;
    if (gtid < N_PC + N_REF) {
        if (gtid < N_PC) {
            float m = FINF;
#pragma unroll
            for (int y = 0; y < YT_A; y++)
                m = fminf(m, __ldcg(&g_partA[y * N_PC + gtid]));
            local = (double)sqrtf(fmaxf(m, 0.0f)) * (0.5 / (double)N_PC);
        } else {
            int i = gtid - N_PC;
            float m = FINF;
#pragma unroll
            for (int y = 0; y < YT_B; y++)
                m = fminf(m, __ldcg(&g_partB[y * N_REF + i]));
            local = (double)sqrtf(fmaxf(m, 0.0f)) * (0.5 / (double)N_REF);
        }
    }
    for (int off = 16; off > 0; off >>= 1)
        local += __shfl_down_sync(0xFFFFFFFFu, local, off);
    const int wid = tid >> 5, lid = tid & 31;
    if (lid == 0) warp_s[wid] = local;
    __syncthreads();
    if (wid == 0) {
        local = (lid < 8) ? warp_s[lid] : 0.0;
        for (int off = 4; off > 0; off >>= 1)
            local += __shfl_down_sync(0xFFFFFFFFu, local, off);
        if (lid == 0) {
            if (local != 0.0) atomicAdd(&g_sum, local);
            __threadfence();
            unsigned t = atomicAdd(&g_done, 1u);
            if (t == GRID - 1) {
                // last block out: publish result and reset ALL state for replay
                double s = *((volatile double*)&g_sum);
                out[0] = (float)s;
                g_sum = 0.0;
                g_bar1 = 0u; g_bar2 = 0u; g_ticket = 0u; g_done = 0u;
                __threadfence();
            }
        }
    }
}

extern "C" void kernel_launch(void* const* d_in, const int* in_sizes, int n_in,
                              void* d_out, int out_size)
{
    const float* pc_src  = (const float*)d_in[0];  // (1000,64,2) fp32
    const float* ref_src = (const float*)d_in[1];  // (80000,2)  fp32
    float* out = (float*)d_out;

    chamfer_kernel<<<GRID, THREADS>>>(pc_src, ref_src, out);
}